// round 1
// baseline (speedup 1.0000x reference)
#include <cuda_runtime.h>
#include <cuda_bf16.h>
#include <math.h>

// ---------------- constants ----------------
#define DM 2048       // d_model
#define NH 16         // heads
#define HD 128        // qk head dim == v head dim
#define LORA 512
#define SEQ 2048
#define BATCH 2
#define ROWS (BATCH*SEQ)   // 4096

// ---------------- scratch (device globals; no allocation allowed) ----------------
__device__ float g_kvlat[ROWS * LORA];     // 8 MB
__device__ float g_k[ROWS * DM];           // 32 MB
__device__ float g_v[ROWS * DM];           // 32 MB
__device__ float g_q[ROWS * DM];           // 32 MB
__device__ float g_attn[ROWS * DM];        // 32 MB

// ---------------- SGEMM: C[M,N] = A[M,K] @ B[K,N], all row-major ----------------
// 128x128 tile, BK=8, 256 threads, 8x8 register microtile.
__global__ __launch_bounds__(256) void sgemm_kernel(
    const float* __restrict__ A, const float* __restrict__ B, float* __restrict__ C,
    int M, int N, int K)
{
    __shared__ float As[8][128];
    __shared__ float Bs[8][128];

    const int bx = blockIdx.x;            // N tile
    const int by = blockIdx.y;            // M tile
    const int tid = threadIdx.x;
    const int tx = tid & 15;              // 0..15 -> cols tx*8..+7
    const int ty = tid >> 4;              // 0..15 -> rows ty*8..+7

    const float* Ab = A + (size_t)(by * 128) * K;
    const float* Bb = B + (size_t)(bx * 128);

    const int arow = tid >> 1;            // 0..127
    const int acol = (tid & 1) * 4;       // 0 or 4
    const int brow = tid >> 5;            // 0..7
    const int bcol = (tid & 31) * 4;      // 0..124

    float acc[8][8];
#pragma unroll
    for (int i = 0; i < 8; i++)
#pragma unroll
        for (int j = 0; j < 8; j++) acc[i][j] = 0.f;

    for (int k0 = 0; k0 < K; k0 += 8) {
        float4 av = *(const float4*)(Ab + (size_t)arow * K + k0 + acol);
        As[acol + 0][arow] = av.x;
        As[acol + 1][arow] = av.y;
        As[acol + 2][arow] = av.z;
        As[acol + 3][arow] = av.w;
        *(float4*)(&Bs[brow][bcol]) = *(const float4*)(Bb + (size_t)(k0 + brow) * N + bcol);
        __syncthreads();

#pragma unroll
        for (int kk = 0; kk < 8; kk++) {
            float a[8], b[8];
            *(float4*)(a)     = *(const float4*)(&As[kk][ty * 8]);
            *(float4*)(a + 4) = *(const float4*)(&As[kk][ty * 8 + 4]);
            *(float4*)(b)     = *(const float4*)(&Bs[kk][tx * 8]);
            *(float4*)(b + 4) = *(const float4*)(&Bs[kk][tx * 8 + 4]);
#pragma unroll
            for (int i = 0; i < 8; i++)
#pragma unroll
                for (int j = 0; j < 8; j++) acc[i][j] += a[i] * b[j];
        }
        __syncthreads();
    }

    float* Cb = C + (size_t)(by * 128 + ty * 8) * N + bx * 128 + tx * 8;
#pragma unroll
    for (int i = 0; i < 8; i++) {
        float4 lo = make_float4(acc[i][0], acc[i][1], acc[i][2], acc[i][3]);
        float4 hi = make_float4(acc[i][4], acc[i][5], acc[i][6], acc[i][7]);
        *(float4*)(Cb + (size_t)i * N)     = lo;
        *(float4*)(Cb + (size_t)i * N + 4) = hi;
    }
}

// ---------------- RMS norm over rows of 512, in place ----------------
__global__ __launch_bounds__(256) void rmsnorm_kernel(float* __restrict__ x,
                                                      const float* __restrict__ w)
{
    const int row = blockIdx.x;
    float* p = x + (size_t)row * LORA;
    const int t = threadIdx.x;
    float v0 = p[t];
    float v1 = p[t + 256];
    float ss = v0 * v0 + v1 * v1;
#pragma unroll
    for (int o = 16; o; o >>= 1) ss += __shfl_xor_sync(0xffffffffu, ss, o);
    __shared__ float sred[8];
    if ((t & 31) == 0) sred[t >> 5] = ss;
    __syncthreads();
    float tot = 0.f;
#pragma unroll
    for (int i = 0; i < 8; i++) tot += sred[i];
    float inv = rsqrtf(tot * (1.0f / (float)LORA) + 1e-6f);
    p[t]       = v0 * inv * w[t];
    p[t + 256] = v1 * inv * w[t + 256];
}

// ---------------- RoPE (interleaved pairs), in place on [ROWS, NH, HD] ----------------
__global__ __launch_bounds__(256) void rope_kernel(float* __restrict__ t,
                                                   const float* __restrict__ fc,
                                                   const float* __restrict__ fs)
{
    int idx = blockIdx.x * 256 + threadIdx.x;   // ROWS*NH*64 pairs
    if (idx >= ROWS * NH * 64) return;
    int p   = idx & 63;
    int h   = (idx >> 6) & 15;
    int row = idx >> 10;
    int s   = row & (SEQ - 1);
    float c  = fc[s * 64 + p];
    float sn = fs[s * 64 + p];
    float* base = t + (size_t)row * DM + h * HD + p * 2;
    float x1 = base[0], x2 = base[1];
    base[0] = x1 * c - x2 * sn;
    base[1] = x1 * sn + x2 * c;
}

// ---------------- Flash attention (causal), fp32 ----------------
// One block per (b, h, q-tile of 128). BN=64 kv per inner tile.
// Threads: 256 = 16(tx) x 16(ty). ty owns 8 q rows; tx interleaves k cols (c*16+tx)
// and v dims (jj*16+tx) for conflict-free smem access.
#define QS_STRIDE 132
#define FLASH_SMEM ((128*QS_STRIDE + 64*QS_STRIDE + 64*QS_STRIDE + 128*64) * 4)

__global__ __launch_bounds__(256) void flash_kernel(
    const float* __restrict__ Q, const float* __restrict__ K,
    const float* __restrict__ V, float* __restrict__ O)
{
    extern __shared__ float sm[];
    float* Qs = sm;                           // 128 x 132
    float* Ks = Qs + 128 * QS_STRIDE;         // 64 x 132
    float* Vs = Ks + 64 * QS_STRIDE;          // 64 x 132
    float* Ps = Vs + 64 * QS_STRIDE;          // 128 x 64

    const int qt = blockIdx.x;                // q tile (128 rows)
    const int h  = blockIdx.y;
    const int b  = blockIdx.z;
    const int tid = threadIdx.x;
    const int tx = tid & 15;
    const int ty = tid >> 4;

    const int row0 = b * SEQ + qt * 128;
    const size_t hoff = (size_t)h * HD;

    // load Q tile (128 x 128)
    for (int t = tid; t < 128 * 32; t += 256) {
        int r = t >> 5, c4 = (t & 31) << 2;
        *(float4*)(Qs + r * QS_STRIDE + c4) =
            *(const float4*)(Q + (size_t)(row0 + r) * DM + hoff + c4);
    }

    float m[8], l[8], o[8][8];
#pragma unroll
    for (int i = 0; i < 8; i++) {
        m[i] = -INFINITY; l[i] = 0.f;
#pragma unroll
        for (int j = 0; j < 8; j++) o[i][j] = 0.f;
    }
    const float scale = 0.08838834764831845f;  // 1/sqrt(128)

    const int jt_max = 2 * qt + 1;
    for (int jt = 0; jt <= jt_max; jt++) {
        __syncthreads();   // previous iteration's smem reads done
        const int krow0 = b * SEQ + jt * 64;
        for (int t = tid; t < 64 * 32; t += 256) {
            int r = t >> 5, c4 = (t & 31) << 2;
            *(float4*)(Ks + r * QS_STRIDE + c4) =
                *(const float4*)(K + (size_t)(krow0 + r) * DM + hoff + c4);
            *(float4*)(Vs + r * QS_STRIDE + c4) =
                *(const float4*)(V + (size_t)(krow0 + r) * DM + hoff + c4);
        }
        __syncthreads();

        // ---- scores s[i][c] for k = c*16+tx ----
        float s[8][4];
#pragma unroll
        for (int i = 0; i < 8; i++)
#pragma unroll
            for (int c = 0; c < 4; c++) s[i][c] = 0.f;

        for (int kk = 0; kk < HD; kk += 4) {
            float4 kv[4];
#pragma unroll
            for (int c = 0; c < 4; c++)
                kv[c] = *(const float4*)(Ks + (c * 16 + tx) * QS_STRIDE + kk);
#pragma unroll
            for (int i = 0; i < 8; i++) {
                float4 a = *(const float4*)(Qs + (ty * 8 + i) * QS_STRIDE + kk);
#pragma unroll
                for (int c = 0; c < 4; c++)
                    s[i][c] += a.x * kv[c].x + a.y * kv[c].y + a.z * kv[c].z + a.w * kv[c].w;
            }
        }

        // scale + causal mask (only tiles on/above diagonal need it)
        const bool need_mask = (jt >= 2 * qt);
#pragma unroll
        for (int i = 0; i < 8; i++) {
            int qg = qt * 128 + ty * 8 + i;
#pragma unroll
            for (int c = 0; c < 4; c++) {
                s[i][c] *= scale;
                if (need_mask) {
                    int kg = jt * 64 + c * 16 + tx;
                    if (kg > qg) s[i][c] = -INFINITY;
                }
            }
        }

        // ---- online softmax ----
        float fac[8];
#pragma unroll
        for (int i = 0; i < 8; i++) {
            float mt = fmaxf(fmaxf(s[i][0], s[i][1]), fmaxf(s[i][2], s[i][3]));
#pragma unroll
            for (int off = 8; off; off >>= 1)
                mt = fmaxf(mt, __shfl_xor_sync(0xffffffffu, mt, off, 16));
            float mn = fmaxf(m[i], mt);
            fac[i] = __expf(m[i] - mn);
            m[i] = mn;
            float rs = 0.f;
#pragma unroll
            for (int c = 0; c < 4; c++) {
                float p = __expf(s[i][c] - mn);
                Ps[(ty * 8 + i) * 64 + c * 16 + tx] = p;
                rs += p;
            }
#pragma unroll
            for (int off = 8; off; off >>= 1)
                rs += __shfl_xor_sync(0xffffffffu, rs, off, 16);
            l[i] = l[i] * fac[i] + rs;
#pragma unroll
            for (int j = 0; j < 8; j++) o[i][j] *= fac[i];
        }
        __syncthreads();   // Ps visible

        // ---- o += P @ V ;  v dim = jj*16+tx ----
        for (int k = 0; k < 64; k++) {
            float vv[8];
#pragma unroll
            for (int jj = 0; jj < 8; jj++)
                vv[jj] = Vs[k * QS_STRIDE + jj * 16 + tx];
#pragma unroll
            for (int i = 0; i < 8; i++) {
                float p = Ps[(ty * 8 + i) * 64 + k];
#pragma unroll
                for (int jj = 0; jj < 8; jj++) o[i][jj] += p * vv[jj];
            }
        }
    }

    // epilogue: normalize, write attn[row][h*128 + v]
#pragma unroll
    for (int i = 0; i < 8; i++) {
        float inv = 1.0f / l[i];
        float* op = O + (size_t)(row0 + ty * 8 + i) * DM + hoff;
#pragma unroll
        for (int jj = 0; jj < 8; jj++)
            op[jj * 16 + tx] = o[i][jj] * inv;
    }
}

// ---------------- launch ----------------
extern "C" void kernel_launch(void* const* d_in, const int* in_sizes, int n_in,
                              void* d_out, int out_size)
{
    const float* x     = (const float*)d_in[0];
    const float* fcos  = (const float*)d_in[1];
    const float* fsin  = (const float*)d_in[2];
    const float* w_kvc = (const float*)d_in[3];
    const float* kvw   = (const float*)d_in[4];
    const float* w_k   = (const float*)d_in[5];
    const float* w_v   = (const float*)d_in[6];
    const float* w_q   = (const float*)d_in[7];
    const float* w_o   = (const float*)d_in[8];
    float* out = (float*)d_out;

    float *kvl, *Kb, *Vb, *Qb, *Ab;
    cudaGetSymbolAddress((void**)&kvl, g_kvlat);
    cudaGetSymbolAddress((void**)&Kb, g_k);
    cudaGetSymbolAddress((void**)&Vb, g_v);
    cudaGetSymbolAddress((void**)&Qb, g_q);
    cudaGetSymbolAddress((void**)&Ab, g_attn);

    cudaFuncSetAttribute(flash_kernel, cudaFuncAttributeMaxDynamicSharedMemorySize,
                         FLASH_SMEM);

    // 1) kv_compressed = x @ w_kv_compress   [4096, 512]
    sgemm_kernel<<<dim3(LORA / 128, ROWS / 128), 256>>>(x, w_kvc, kvl, ROWS, LORA, DM);
    // 2) rmsnorm in place
    rmsnorm_kernel<<<ROWS, 256>>>(kvl, kvw);
    // 3) k = kv_latent @ w_k_up   [4096, 2048]
    sgemm_kernel<<<dim3(DM / 128, ROWS / 128), 256>>>(kvl, w_k, Kb, ROWS, DM, LORA);
    // 4) v = kv_latent @ w_v_up   [4096, 2048]
    sgemm_kernel<<<dim3(DM / 128, ROWS / 128), 256>>>(kvl, w_v, Vb, ROWS, DM, LORA);
    // 5) q = x @ w_q   [4096, 2048]
    sgemm_kernel<<<dim3(DM / 128, ROWS / 128), 256>>>(x, w_q, Qb, ROWS, DM, DM);
    // 6) RoPE on q and k
    int rope_threads = ROWS * NH * 64;
    rope_kernel<<<(rope_threads + 255) / 256, 256>>>(Qb, fcos, fsin);
    rope_kernel<<<(rope_threads + 255) / 256, 256>>>(Kb, fcos, fsin);
    // 7) causal flash attention -> attn [4096, 2048]
    flash_kernel<<<dim3(SEQ / 128, NH, BATCH), 256, FLASH_SMEM>>>(Qb, Kb, Vb, Ab);
    // 8) out = attn @ w_out
    sgemm_kernel<<<dim3(DM / 128, ROWS / 128), 256>>>(Ab, w_o, out, ROWS, DM, DM);
}

// round 4
// speedup vs baseline: 3.2649x; 3.2649x over previous
#include <cuda_runtime.h>
#include <cstdint>
#include <math.h>

// ---------------- constants ----------------
#define DM 2048
#define NH 16
#define HD 128
#define LORA 512
#define SEQ 2048
#define BATCH 2
#define ROWS (BATCH*SEQ)   // 4096

// ---------------- scratch ----------------
__device__ float g_xc[ROWS * DM];
__device__ float g_kvlat[ROWS * LORA];
__device__ float g_k[ROWS * DM];
__device__ float g_v[ROWS * DM];
__device__ float g_q[ROWS * DM];
__device__ float g_vT[BATCH * NH * HD * SEQ];
__device__ float g_attn[ROWS * DM];
__device__ float g_wkvcT[LORA * DM];
__device__ float g_wkT[DM * LORA];
__device__ float g_wvT[DM * LORA];
__device__ float g_wqT[DM * DM];
__device__ float g_woT[DM * DM];

// ---------------- helpers ----------------
__device__ __forceinline__ uint32_t rna_u(float x) {
    uint32_t u; asm("cvt.rna.tf32.f32 %0, %1;" : "=r"(u) : "f"(x)); return u;
}
__device__ __forceinline__ float rna_f(float x) { return __uint_as_float(rna_u(x)); }

__device__ __forceinline__ uint32_t smem_addr(const void* p) {
    return (uint32_t)__cvta_generic_to_shared(p);
}
__device__ __forceinline__ void cpasync16(uint32_t s, const void* g) {
    asm volatile("cp.async.cg.shared.global [%0], [%1], 16;" :: "r"(s), "l"(g));
}
#define CP_COMMIT asm volatile("cp.async.commit_group;" ::: "memory")
#define CP_WAIT0  asm volatile("cp.async.wait_group 0;" ::: "memory")
#define CP_WAIT3  asm volatile("cp.async.wait_group 3;" ::: "memory")

// mma.sync m16n8k8 tf32: D += A@B ; A row-major, B col-major
__device__ __forceinline__ void mma8(float* c, const uint32_t* a, const uint32_t* b) {
    asm volatile(
        "mma.sync.aligned.m16n8k8.row.col.f32.tf32.tf32.f32 "
        "{%0,%1,%2,%3}, {%4,%5,%6,%7}, {%8,%9}, {%0,%1,%2,%3};"
        : "+f"(c[0]), "+f"(c[1]), "+f"(c[2]), "+f"(c[3])
        : "r"(a[0]), "r"(a[1]), "r"(a[2]), "r"(a[3]), "r"(b[0]), "r"(b[1]));
}

// ================= tf32 mma.sync GEMM =================
// C[M,N] = A[M,K] @ Bt[N,K]^T ; CTA tile 128x128, BK=32, 8 warps (warp 64x32).
#define GSTAGES 4
#define GSTR 36                      // padded smem stride (floats)
#define GSTAGE_F (128*GSTR*2)        // A + B floats per stage
#define GEMM_SMEM (GSTAGES*GSTAGE_F*4)

__global__ __launch_bounds__(256, 1)
void gemm_tf32(const float* __restrict__ A, const float* __restrict__ Bt,
               float* __restrict__ C, int M, int N, int K)
{
    extern __shared__ float sm[];
    const int tid = threadIdx.x, wid = tid >> 5, lane = tid & 31;
    const int g = lane >> 2, tg = lane & 3;
    const int wm = wid >> 2, wn = wid & 3;     // 2 x 4 warp grid
    const int m0 = blockIdx.y * 128, n0 = blockIdx.x * 128;
    const int NC = K >> 5;

    float c[4][4][4];
#pragma unroll
    for (int mt = 0; mt < 4; mt++)
#pragma unroll
        for (int nt = 0; nt < 4; nt++)
#pragma unroll
            for (int j = 0; j < 4; j++) c[mt][nt][j] = 0.f;

    auto load_chunk = [&](int stage, int ch) {
        float* As = sm + stage * GSTAGE_F;
        float* Bs = As + 128 * GSTR;
        const float* Ag = A + (size_t)m0 * K + ch * 32;
        const float* Bg = Bt + (size_t)n0 * K + ch * 32;
#pragma unroll
        for (int i = 0; i < 4; i++) {
            int idx = tid + i * 256;
            int row = idx >> 3, c4 = (idx & 7) << 2;
            cpasync16(smem_addr(As + row * GSTR + c4), Ag + (size_t)row * K + c4);
        }
#pragma unroll
        for (int i = 0; i < 4; i++) {
            int idx = tid + i * 256;
            int row = idx >> 3, c4 = (idx & 7) << 2;
            cpasync16(smem_addr(Bs + row * GSTR + c4), Bg + (size_t)row * K + c4);
        }
    };

    // prologue: 3 chunks in flight
    for (int ch = 0; ch < GSTAGES - 1 && ch < NC; ch++) { load_chunk(ch & 3, ch); CP_COMMIT; }

    for (int ch = 0; ch < NC; ch++) {
        __syncthreads();                   // all reads of the stage being overwritten done
        int pf = ch + GSTAGES - 1;
        if (pf < NC) load_chunk(pf & 3, pf);
        CP_COMMIT;
        CP_WAIT3;                          // chunk ch resident (this thread)
        __syncthreads();                   // visible to all

        const float* As = sm + (ch & 3) * GSTAGE_F;
        const float* Bs = As + 128 * GSTR;
#pragma unroll
        for (int ks = 0; ks < 4; ks++) {
            const int kk = ks * 8;
            uint32_t a[4][4], b[4][2];
#pragma unroll
            for (int mt = 0; mt < 4; mt++) {
                const float* p0 = As + (wm * 64 + mt * 16 + g) * GSTR + kk;
                const float* p1 = p0 + 8 * GSTR;
                a[mt][0] = __float_as_uint(p0[tg]);
                a[mt][1] = __float_as_uint(p1[tg]);
                a[mt][2] = __float_as_uint(p0[tg + 4]);
                a[mt][3] = __float_as_uint(p1[tg + 4]);
            }
#pragma unroll
            for (int nt = 0; nt < 4; nt++) {
                const float* p = Bs + (wn * 32 + nt * 8 + g) * GSTR + kk;
                b[nt][0] = __float_as_uint(p[tg]);
                b[nt][1] = __float_as_uint(p[tg + 4]);
            }
#pragma unroll
            for (int mt = 0; mt < 4; mt++)
#pragma unroll
                for (int nt = 0; nt < 4; nt++)
                    mma8(c[mt][nt], a[mt], b[nt]);
        }
    }

    // epilogue
#pragma unroll
    for (int mt = 0; mt < 4; mt++) {
        int row = m0 + wm * 64 + mt * 16 + g;
#pragma unroll
        for (int nt = 0; nt < 4; nt++) {
            int col = n0 + wn * 32 + nt * 8 + 2 * tg;
            *(float2*)&C[(size_t)row * N + col] = make_float2(c[mt][nt][0], c[mt][nt][1]);
            *(float2*)&C[(size_t)(row + 8) * N + col] = make_float2(c[mt][nt][2], c[mt][nt][3]);
        }
    }
}

// ================= flash attention (causal), tf32 mma.sync =================
// BM=128 q rows, BN=64 kv per tile. 8 warps: 4(m) x 2(n).
#define QSTR 132
#define PSTR 68
#define F_QF (128*QSTR)
#define F_KF (64*QSTR)
#define F_VF (128*PSTR)
#define F_PF (128*PSTR)
#define FLASH_SMEM ((F_QF + F_KF + F_VF + F_PF) * 4)

__global__ __launch_bounds__(256, 1)
void flash_tc(const float* __restrict__ Q, const float* __restrict__ K,
              const float* __restrict__ Vt, float* __restrict__ O)
{
    extern __shared__ float sm[];
    float* Qs = sm;
    float* Ks = Qs + F_QF;
    float* Vs = Ks + F_KF;
    float* Ps = Vs + F_VF;
    __shared__ float ex_m[2][128];
    __shared__ float ex_s[2][128];

    const int tid = threadIdx.x, wid = tid >> 5, lane = tid & 31;
    const int g = lane >> 2, tg = lane & 3;
    const int mw = wid & 3, nw = wid >> 2;
    const int qt = blockIdx.x, h = blockIdx.y, b = blockIdx.z;
    const int row0 = b * SEQ + qt * 128;
    const int bh = b * NH + h;
    const float scale = 0.08838834764831845f;

    // load Q tile (128 x 128) = 4096 float4
#pragma unroll
    for (int i = 0; i < 16; i++) {
        int idx = tid + i * 256;
        int row = idx >> 5, c4 = (idx & 31) << 2;
        cpasync16(smem_addr(Qs + row * QSTR + c4),
                  Q + (size_t)(row0 + row) * DM + h * HD + c4);
    }
    CP_COMMIT; CP_WAIT0;
    __syncthreads();

    float o[2][8][4];
    float mrun[2][2], lrun[2][2];
#pragma unroll
    for (int mt = 0; mt < 2; mt++) {
        mrun[mt][0] = mrun[mt][1] = -INFINITY;
        lrun[mt][0] = lrun[mt][1] = 0.f;
#pragma unroll
        for (int nt = 0; nt < 8; nt++)
#pragma unroll
            for (int j = 0; j < 4; j++) o[mt][nt][j] = 0.f;
    }

    const int ntiles = 2 * qt + 2;
    for (int jt = 0; jt < ntiles; jt++) {
        const int kv0 = jt * 64;
        __syncthreads();   // prev-iter reads of Ks/Vs/Ps done
        // load K (64 x 128) = 2048 float4
#pragma unroll
        for (int i = 0; i < 8; i++) {
            int idx = tid + i * 256;
            int row = idx >> 5, c4 = (idx & 31) << 2;
            cpasync16(smem_addr(Ks + row * QSTR + c4),
                      K + (size_t)(b * SEQ + kv0 + row) * DM + h * HD + c4);
        }
        // load Vt (128 x 64) = 2048 float4
#pragma unroll
        for (int i = 0; i < 8; i++) {
            int idx = tid + i * 256;
            int row = idx >> 4, c4 = (idx & 15) << 2;
            cpasync16(smem_addr(Vs + row * PSTR + c4),
                      Vt + (size_t)(bh * HD + row) * SEQ + kv0 + c4);
        }
        CP_COMMIT; CP_WAIT0;
        __syncthreads();

        // ---- S = Q @ K^T : warp computes rows mw*32..+31, kv cols nw*32..+31
        float sc[2][4][4];
#pragma unroll
        for (int mt = 0; mt < 2; mt++)
#pragma unroll
            for (int nt = 0; nt < 4; nt++)
#pragma unroll
                for (int j = 0; j < 4; j++) sc[mt][nt][j] = 0.f;

#pragma unroll
        for (int ks = 0; ks < 16; ks++) {
            const int kk = ks * 8;
            uint32_t a[2][4], bfr[4][2];
#pragma unroll
            for (int mt = 0; mt < 2; mt++) {
                const float* p0 = Qs + (mw * 32 + mt * 16 + g) * QSTR + kk;
                const float* p1 = p0 + 8 * QSTR;
                a[mt][0] = __float_as_uint(p0[tg]);
                a[mt][1] = __float_as_uint(p1[tg]);
                a[mt][2] = __float_as_uint(p0[tg + 4]);
                a[mt][3] = __float_as_uint(p1[tg + 4]);
            }
#pragma unroll
            for (int nt = 0; nt < 4; nt++) {
                const float* p = Ks + (nw * 32 + nt * 8 + g) * QSTR + kk;
                bfr[nt][0] = __float_as_uint(p[tg]);
                bfr[nt][1] = __float_as_uint(p[tg + 4]);
            }
#pragma unroll
            for (int mt = 0; mt < 2; mt++)
#pragma unroll
                for (int nt = 0; nt < 4; nt++)
                    mma8(sc[mt][nt], a[mt], bfr[nt]);
        }

        // ---- scale + causal mask
        const bool need_mask = (jt >= 2 * qt);
#pragma unroll
        for (int mt = 0; mt < 2; mt++)
#pragma unroll
            for (int nt = 0; nt < 4; nt++)
#pragma unroll
                for (int j = 0; j < 4; j++) {
                    float s = sc[mt][nt][j] * scale;
                    if (need_mask) {
                        int qr = qt * 128 + mw * 32 + mt * 16 + g + ((j >= 2) ? 8 : 0);
                        int kc = kv0 + nw * 32 + nt * 8 + 2 * tg + (j & 1);
                        if (kc > qr) s = -1e30f;
                    }
                    sc[mt][nt][j] = s;
                }

        // ---- row max (quad shuffle), cross n-warp via smem
#pragma unroll
        for (int mt = 0; mt < 2; mt++)
#pragma unroll
            for (int hh = 0; hh < 2; hh++) {
                float mx = -INFINITY;
#pragma unroll
                for (int nt = 0; nt < 4; nt++)
                    mx = fmaxf(mx, fmaxf(sc[mt][nt][hh * 2], sc[mt][nt][hh * 2 + 1]));
                mx = fmaxf(mx, __shfl_xor_sync(0xffffffffu, mx, 1));
                mx = fmaxf(mx, __shfl_xor_sync(0xffffffffu, mx, 2));
                ex_m[nw][mw * 32 + mt * 16 + g + hh * 8] = mx;
            }
        __syncthreads();

        // ---- exp, P store, row sums, o rescale
        float fac[2][2];
#pragma unroll
        for (int mt = 0; mt < 2; mt++)
#pragma unroll
            for (int hh = 0; hh < 2; hh++) {
                int rl = mw * 32 + mt * 16 + g + hh * 8;
                float mn = fmaxf(mrun[mt][hh], fmaxf(ex_m[0][rl], ex_m[1][rl]));
                float f = __expf(mrun[mt][hh] - mn);
                mrun[mt][hh] = mn;
                fac[mt][hh] = f;
                float sum = 0.f;
#pragma unroll
                for (int nt = 0; nt < 4; nt++) {
                    float p0 = __expf(sc[mt][nt][hh * 2] - mn);
                    float p1 = __expf(sc[mt][nt][hh * 2 + 1] - mn);
                    sum += p0 + p1;
                    int col = nw * 32 + nt * 8 + 2 * tg;
                    *(float2*)&Ps[rl * PSTR + col] = make_float2(rna_f(p0), rna_f(p1));
                }
                sum += __shfl_xor_sync(0xffffffffu, sum, 1);
                sum += __shfl_xor_sync(0xffffffffu, sum, 2);
                ex_s[nw][rl] = sum;
            }
        // rescale o
#pragma unroll
        for (int mt = 0; mt < 2; mt++)
#pragma unroll
            for (int nt = 0; nt < 8; nt++) {
                o[mt][nt][0] *= fac[mt][0];
                o[mt][nt][1] *= fac[mt][0];
                o[mt][nt][2] *= fac[mt][1];
                o[mt][nt][3] *= fac[mt][1];
            }
        __syncthreads();   // P + ex_s visible
#pragma unroll
        for (int mt = 0; mt < 2; mt++)
#pragma unroll
            for (int hh = 0; hh < 2; hh++) {
                int rl = mw * 32 + mt * 16 + g + hh * 8;
                lrun[mt][hh] = lrun[mt][hh] * fac[mt][hh] + ex_s[0][rl] + ex_s[1][rl];
            }

        // ---- O += P @ V : warp rows mw*32..+31, hd cols nw*64..+63
#pragma unroll
        for (int ks = 0; ks < 8; ks++) {
            const int kk = ks * 8;
            uint32_t a[2][4], bfr[8][2];
#pragma unroll
            for (int mt = 0; mt < 2; mt++) {
                const float* p0 = Ps + (mw * 32 + mt * 16 + g) * PSTR + kk;
                const float* p1 = p0 + 8 * PSTR;
                a[mt][0] = __float_as_uint(p0[tg]);
                a[mt][1] = __float_as_uint(p1[tg]);
                a[mt][2] = __float_as_uint(p0[tg + 4]);
                a[mt][3] = __float_as_uint(p1[tg + 4]);
            }
#pragma unroll
            for (int nt = 0; nt < 8; nt++) {
                const float* p = Vs + (nw * 64 + nt * 8 + g) * PSTR + kk;
                bfr[nt][0] = __float_as_uint(p[tg]);
                bfr[nt][1] = __float_as_uint(p[tg + 4]);
            }
#pragma unroll
            for (int mt = 0; mt < 2; mt++)
#pragma unroll
                for (int nt = 0; nt < 8; nt++)
                    mma8(o[mt][nt], a[mt], bfr[nt]);
        }
    }

    // ---- epilogue: normalize + rna (feeds tf32 w_out GEMM)
#pragma unroll
    for (int mt = 0; mt < 2; mt++) {
        float inv0 = 1.0f / lrun[mt][0];
        float inv1 = 1.0f / lrun[mt][1];
        int row = row0 + mw * 32 + mt * 16 + g;
#pragma unroll
        for (int nt = 0; nt < 8; nt++) {
            int col = h * HD + nw * 64 + nt * 8 + 2 * tg;
            *(float2*)&O[(size_t)row * DM + col] =
                make_float2(rna_f(o[mt][nt][0] * inv0), rna_f(o[mt][nt][1] * inv0));
            *(float2*)&O[(size_t)(row + 8) * DM + col] =
                make_float2(rna_f(o[mt][nt][2] * inv1), rna_f(o[mt][nt][3] * inv1));
        }
    }
}

// ---------------- small kernels ----------------
__global__ __launch_bounds__(256) void cvtx_kernel(const float* __restrict__ x,
                                                   float* __restrict__ y, int n4)
{
    int i = blockIdx.x * 256 + threadIdx.x;
    if (i >= n4) return;
    float4 v = ((const float4*)x)[i];
    ((float4*)y)[i] = make_float4(rna_f(v.x), rna_f(v.y), rna_f(v.z), rna_f(v.w));
}

__global__ __launch_bounds__(256) void trans_cvt(const float* __restrict__ src,
                                                 float* __restrict__ dst, int R, int C)
{
    __shared__ float t[32][33];
    int c0 = blockIdx.x * 32, r0 = blockIdx.y * 32;
    int tx = threadIdx.x & 31, ty = threadIdx.x >> 5;
#pragma unroll
    for (int i = 0; i < 4; i++)
        t[ty + i * 8][tx] = src[(size_t)(r0 + ty + i * 8) * C + c0 + tx];
    __syncthreads();
#pragma unroll
    for (int i = 0; i < 4; i++)
        dst[(size_t)(c0 + ty + i * 8) * R + r0 + tx] = rna_f(t[tx][ty + i * 8]);
}

__global__ __launch_bounds__(256) void vtrans_kernel(const float* __restrict__ v,
                                                     float* __restrict__ vt)
{
    __shared__ float t[32][33];
    int bh = blockIdx.z;
    int b = bh >> 4, h = bh & 15;
    int s0 = blockIdx.x * 32, d0 = blockIdx.y * 32;
    int tx = threadIdx.x & 31, ty = threadIdx.x >> 5;
#pragma unroll
    for (int i = 0; i < 4; i++)
        t[ty + i * 8][tx] = v[(size_t)(b * SEQ + s0 + ty + i * 8) * DM + h * HD + d0 + tx];
    __syncthreads();
#pragma unroll
    for (int i = 0; i < 4; i++)
        vt[(size_t)(bh * HD + d0 + ty + i * 8) * SEQ + s0 + tx] = rna_f(t[tx][ty + i * 8]);
}

__global__ __launch_bounds__(256) void rmsnorm_kernel(float* __restrict__ x,
                                                      const float* __restrict__ w)
{
    const int row = blockIdx.x;
    float* p = x + (size_t)row * LORA;
    const int t = threadIdx.x;
    float v0 = p[t], v1 = p[t + 256];
    float ss = v0 * v0 + v1 * v1;
#pragma unroll
    for (int o = 16; o; o >>= 1) ss += __shfl_xor_sync(0xffffffffu, ss, o);
    __shared__ float sred[8];
    if ((t & 31) == 0) sred[t >> 5] = ss;
    __syncthreads();
    float tot = 0.f;
#pragma unroll
    for (int i = 0; i < 8; i++) tot += sred[i];
    float inv = rsqrtf(tot * (1.0f / (float)LORA) + 1e-6f);
    p[t]       = rna_f(v0 * inv * w[t]);
    p[t + 256] = rna_f(v1 * inv * w[t + 256]);
}

__global__ __launch_bounds__(256) void rope_kernel(float* __restrict__ t,
                                                   const float* __restrict__ fc,
                                                   const float* __restrict__ fs)
{
    int idx = blockIdx.x * 256 + threadIdx.x;
    if (idx >= ROWS * NH * 64) return;
    int p = idx & 63, h = (idx >> 6) & 15, row = idx >> 10;
    int s = row & (SEQ - 1);
    float c = fc[s * 64 + p], sn = fs[s * 64 + p];
    float* base = t + (size_t)row * DM + h * HD + p * 2;
    float x1 = base[0], x2 = base[1];
    base[0] = rna_f(x1 * c - x2 * sn);
    base[1] = rna_f(x1 * sn + x2 * c);
}

// ---------------- launch ----------------
extern "C" void kernel_launch(void* const* d_in, const int* in_sizes, int n_in,
                              void* d_out, int out_size)
{
    const float* x     = (const float*)d_in[0];
    const float* fcos  = (const float*)d_in[1];
    const float* fsin  = (const float*)d_in[2];
    const float* w_kvc = (const float*)d_in[3];
    const float* kvw   = (const float*)d_in[4];
    const float* w_k   = (const float*)d_in[5];
    const float* w_v   = (const float*)d_in[6];
    const float* w_q   = (const float*)d_in[7];
    const float* w_o   = (const float*)d_in[8];
    float* out = (float*)d_out;

    float *xc, *kvl, *Kb, *Vb, *Qb, *VT, *Ab;
    float *wkvcT, *wkT, *wvT, *wqT, *woT;
    cudaGetSymbolAddress((void**)&xc, g_xc);
    cudaGetSymbolAddress((void**)&kvl, g_kvlat);
    cudaGetSymbolAddress((void**)&Kb, g_k);
    cudaGetSymbolAddress((void**)&Vb, g_v);
    cudaGetSymbolAddress((void**)&Qb, g_q);
    cudaGetSymbolAddress((void**)&VT, g_vT);
    cudaGetSymbolAddress((void**)&Ab, g_attn);
    cudaGetSymbolAddress((void**)&wkvcT, g_wkvcT);
    cudaGetSymbolAddress((void**)&wkT, g_wkT);
    cudaGetSymbolAddress((void**)&wvT, g_wvT);
    cudaGetSymbolAddress((void**)&wqT, g_wqT);
    cudaGetSymbolAddress((void**)&woT, g_woT);

    cudaFuncSetAttribute(gemm_tf32, cudaFuncAttributeMaxDynamicSharedMemorySize, GEMM_SMEM);
    cudaFuncSetAttribute(flash_tc, cudaFuncAttributeMaxDynamicSharedMemorySize, FLASH_SMEM);

    // tf32-round x
    cvtx_kernel<<<(ROWS * DM / 4 + 255) / 256, 256>>>(x, xc, ROWS * DM / 4);
    // transpose + round weights: src [K,N] -> dst [N,K]
    trans_cvt<<<dim3(LORA / 32, DM / 32), 256>>>(w_kvc, wkvcT, DM, LORA);
    trans_cvt<<<dim3(DM / 32, LORA / 32), 256>>>(w_k, wkT, LORA, DM);
    trans_cvt<<<dim3(DM / 32, LORA / 32), 256>>>(w_v, wvT, LORA, DM);
    trans_cvt<<<dim3(DM / 32, DM / 32), 256>>>(w_q, wqT, DM, DM);
    trans_cvt<<<dim3(DM / 32, DM / 32), 256>>>(w_o, woT, DM, DM);

    // kv_compressed = x @ w_kvc  [4096, 512]
    gemm_tf32<<<dim3(LORA / 128, ROWS / 128), 256, GEMM_SMEM>>>(xc, wkvcT, kvl, ROWS, LORA, DM);
    rmsnorm_kernel<<<ROWS, 256>>>(kvl, kvw);
    // k, v up-projections [4096, 2048]
    gemm_tf32<<<dim3(DM / 128, ROWS / 128), 256, GEMM_SMEM>>>(kvl, wkT, Kb, ROWS, DM, LORA);
    gemm_tf32<<<dim3(DM / 128, ROWS / 128), 256, GEMM_SMEM>>>(kvl, wvT, Vb, ROWS, DM, LORA);
    // q = x @ w_q [4096, 2048]
    gemm_tf32<<<dim3(DM / 128, ROWS / 128), 256, GEMM_SMEM>>>(xc, wqT, Qb, ROWS, DM, DM);
    // RoPE (+tf32 rounding)
    int rope_n = ROWS * NH * 64;
    rope_kernel<<<(rope_n + 255) / 256, 256>>>(Qb, fcos, fsin);
    rope_kernel<<<(rope_n + 255) / 256, 256>>>(Kb, fcos, fsin);
    // V transpose per (b,h)
    vtrans_kernel<<<dim3(SEQ / 32, HD / 32, BATCH * NH), 256>>>(Vb, VT);
    // flash attention
    flash_tc<<<dim3(SEQ / 128, NH, BATCH), 256, FLASH_SMEM>>>(Qb, Kb, VT, Ab);
    // out = attn @ w_out
    gemm_tf32<<<dim3(DM / 128, ROWS / 128), 256, GEMM_SMEM>>>(Ab, woT, out, ROWS, DM, DM);
}